// round 1
// baseline (speedup 1.0000x reference)
#include <cuda_runtime.h>

#define BB 4
#define NN 2048
#define FF 64
#define HH 4

// -------------------- device scratch (no allocations allowed) --------------------
__device__ float g_Wqkv[64 * 192];      // fused Wqc@Wqe, q-cols pre-scaled by 0.25
__device__ float g_bqkv[192];           // fused bqc@Wqe + bqe (q part scaled)
__device__ float g_Wo[64 * 64];         // fused Woc@Woe
__device__ float g_bo[64];              // fused boc@Woe + boe
__device__ float g_fr[1];               // sigmoid(graph_fusion)
__device__ float g_qkv[BB * NN * 192];  // [b][n][q(64) k(64) v(64)], h-major within 64
__device__ float g_ctx[BB * NN * 64];   // attention context

// -------------------- f32x2 helpers (Blackwell packed fp32) --------------------
__device__ __forceinline__ unsigned long long pack2(float x, float y) {
    unsigned long long r;
    asm("mov.b64 %0, {%1, %2};" : "=l"(r) : "f"(x), "f"(y));
    return r;
}
__device__ __forceinline__ void unpack2(unsigned long long v, float& x, float& y) {
    asm("mov.b64 {%0, %1}, %2;" : "=f"(x), "=f"(y) : "l"(v));
}
#define FMA2(d, a, b) asm("fma.rn.f32x2 %0, %1, %2, %0;" : "+l"(d) : "l"(a), "l"(b))

// -------------------- kernel 1: fold the low-rank projections --------------------
__global__ void prep_kernel(const float* __restrict__ Wqc, const float* __restrict__ bqc,
                            const float* __restrict__ Wqe, const float* __restrict__ bqe,
                            const float* __restrict__ Woc, const float* __restrict__ boc,
                            const float* __restrict__ Woe, const float* __restrict__ boe,
                            const float* __restrict__ gf) {
    int tid = threadIdx.x;  // 256 threads
    for (int idx = tid; idx < 64 * 192; idx += 256) {
        int i = idx / 192, j = idx % 192;
        float s = 0.f;
#pragma unroll
        for (int c = 0; c < 24; c++) s += Wqc[i * 24 + c] * Wqe[c * 192 + j];
        if (j < 64) s *= 0.25f;  // fold 1/sqrt(hd)
        g_Wqkv[idx] = s;
    }
    for (int j = tid; j < 192; j += 256) {
        float s = bqe[j];
#pragma unroll
        for (int c = 0; c < 24; c++) s += bqc[c] * Wqe[c * 192 + j];
        if (j < 64) s *= 0.25f;
        g_bqkv[j] = s;
    }
    for (int idx = tid; idx < 64 * 64; idx += 256) {
        int i = idx >> 6, j = idx & 63;
        float s = 0.f;
#pragma unroll
        for (int c = 0; c < 8; c++) s += Woc[i * 8 + c] * Woe[c * 64 + j];
        g_Wo[idx] = s;
    }
    for (int j = tid; j < 64; j += 256) {
        float s = boe[j];
#pragma unroll
        for (int c = 0; c < 8; c++) s += boc[c] * Woe[c * 64 + j];
        g_bo[j] = s;
    }
    if (tid == 0) g_fr[0] = 1.f / (1.f + expf(-gf[0]));
}

// -------------------- kernel 2: fused QKV projection --------------------
__global__ __launch_bounds__(256) void qkv_kernel(const float* __restrict__ feats) {
    __shared__ float sf[32][64];
    __shared__ float4 sW4[64][48];  // 192 floats per row
    int tid = threadIdx.x;
    int row0 = blockIdx.x * 32;
    for (int idx = tid; idx < 64 * 48; idx += 256)
        sW4[idx / 48][idx % 48] = ((const float4*)g_Wqkv)[idx];
    for (int idx = tid; idx < 32 * 64; idx += 256)
        sf[idx >> 6][idx & 63] = feats[(size_t)row0 * 64 + idx];
    __syncthreads();
    int r = tid >> 3, cg = tid & 7;  // 32 rows x 8 col-groups (24 cols each)
    float4 acc[6];
#pragma unroll
    for (int w = 0; w < 6; w++) acc[w] = ((const float4*)g_bqkv)[cg * 6 + w];
#pragma unroll 8
    for (int c = 0; c < 64; c++) {
        float f = sf[r][c];
#pragma unroll
        for (int w = 0; w < 6; w++) {
            float4 wv = sW4[c][cg * 6 + w];
            acc[w].x += f * wv.x; acc[w].y += f * wv.y;
            acc[w].z += f * wv.z; acc[w].w += f * wv.w;
        }
    }
    float4* dst = (float4*)&g_qkv[(size_t)(row0 + r) * 192 + cg * 24];
#pragma unroll
    for (int w = 0; w < 6; w++) dst[w] = acc[w];
}

// -------------------- kernel 3: fused attention (the hot kernel) --------------------
// Grid: 256 CTAs (b x 32-row blocks). CTA: 256 threads = 8 warps.
// Warp w: head h = w&3, phase p = w>>2 (p splits the m dimension by parity).
// Lane = row within the 32-row block. All k/v/bf2 shared reads are warp-uniform
// (pure broadcast). Scores are small -> no max subtraction needed.
__global__ __launch_bounds__(256) void attn_kernel(const float* __restrict__ learned,
                                                   const float* __restrict__ fixedg,
                                                   const float* __restrict__ bf1,
                                                   const float* __restrict__ bf2) {
    __shared__ float skv[32][128];      // k (0..63) | v (64..127) per m
    __shared__ float scomb[32][33];     // fused graph, padded (row-distinct banks)
    __shared__ float sbf2[4][32][8];    // bias factor 2, [h][mi][c]
    __shared__ float sred[4][32][17];   // phase-combine buffer {l, acc[16]}

    int tid = threadIdx.x;
    int lane = tid & 31;
    int w = tid >> 5;
    int h = w & 3, p = w >> 2;
    int bid = blockIdx.x;
    int b = bid >> 6;             // 64 row-blocks per batch
    int n0 = (bid & 63) << 5;     // 32 rows per CTA
    int n = n0 + lane;
    int h16 = h * 16;

    // preload q (pre-scaled by 0.25) and bf1 row as f32x2 pairs
    unsigned long long q2[8], f1p[4];
    {
        const ulonglong2* qp = (const ulonglong2*)(g_qkv + ((size_t)(b * NN + n)) * 192 + h16);
        ulonglong2 a0 = qp[0], a1 = qp[1], a2 = qp[2], a3 = qp[3];
        q2[0] = a0.x; q2[1] = a0.y; q2[2] = a1.x; q2[3] = a1.y;
        q2[4] = a2.x; q2[5] = a2.y; q2[6] = a3.x; q2[7] = a3.y;
        const ulonglong2* fp = (const ulonglong2*)(bf1 + ((size_t)h * NN + n) * 8);
        ulonglong2 f0 = fp[0], f1 = fp[1];
        f1p[0] = f0.x; f1p[1] = f0.y; f1p[2] = f1.x; f1p[3] = f1.y;
    }
    float fr = g_fr[0];
    float fr1 = 1.f - fr;

    unsigned long long acc[8];
#pragma unroll
    for (int j = 0; j < 8; j++) acc[j] = 0ULL;
    float l = 0.f;

    for (int m0 = 0; m0 < NN; m0 += 32) {
        __syncthreads();
        // ---- cooperative tile loads (all coalesced along m) ----
#pragma unroll
        for (int it = 0; it < 4; it++) {
            int e = tid + it * 256;
            int mi = e >> 5, j4 = e & 31;
            float4 val = *(const float4*)(g_qkv + ((size_t)(b * NN + m0 + mi)) * 192 + 64 + j4 * 4);
            *(float4*)&skv[mi][j4 * 4] = val;
        }
        {
            int rl = tid >> 3, c4 = tid & 7;
            float4 lg = *(const float4*)(learned + ((size_t)(b * NN + n0 + rl)) * NN + m0 + c4 * 4);
            float4 fg = *(const float4*)(fixedg + ((size_t)(n0 + rl)) * NN + m0 + c4 * 4);
            scomb[rl][c4 * 4 + 0] = fr * lg.x + fr1 * fg.x;
            scomb[rl][c4 * 4 + 1] = fr * lg.y + fr1 * fg.y;
            scomb[rl][c4 * 4 + 2] = fr * lg.z + fr1 * fg.z;
            scomb[rl][c4 * 4 + 3] = fr * lg.w + fr1 * fg.w;
        }
        {
            int h2 = tid >> 6, rem = tid & 63;
            int c = rem >> 3, m4 = rem & 7;
            float4 bb = *(const float4*)(bf2 + (size_t)h2 * 8 * NN + (size_t)c * NN + m0 + m4 * 4);
            sbf2[h2][m4 * 4 + 0][c] = bb.x;
            sbf2[h2][m4 * 4 + 1][c] = bb.y;
            sbf2[h2][m4 * 4 + 2][c] = bb.z;
            sbf2[h2][m4 * 4 + 3][c] = bb.w;
        }
        __syncthreads();

        // ---- inner loop: 16 m per warp (phase-split) ----
#pragma unroll 4
        for (int i = 0; i < 16; i++) {
            int mi = (i << 1) + p;
            unsigned long long s0 = pack2(scomb[lane][mi], 0.f), s1 = 0ULL;
            const ulonglong2* kp = (const ulonglong2*)&skv[mi][h16];
            ulonglong2 t0 = kp[0]; FMA2(s0, q2[0], t0.x); FMA2(s1, q2[1], t0.y);
            ulonglong2 t1 = kp[1]; FMA2(s0, q2[2], t1.x); FMA2(s1, q2[3], t1.y);
            ulonglong2 t2 = kp[2]; FMA2(s0, q2[4], t2.x); FMA2(s1, q2[5], t2.y);
            ulonglong2 t3 = kp[3]; FMA2(s0, q2[6], t3.x); FMA2(s1, q2[7], t3.y);
            const ulonglong2* bp = (const ulonglong2*)&sbf2[h][mi][0];
            ulonglong2 u0 = bp[0]; FMA2(s0, f1p[0], u0.x); FMA2(s1, f1p[1], u0.y);
            ulonglong2 u1 = bp[1]; FMA2(s0, f1p[2], u1.x); FMA2(s1, f1p[3], u1.y);
            float a0, a1, a2, a3;
            unpack2(s0, a0, a1); unpack2(s1, a2, a3);
            float e = __expf((a0 + a2) + (a1 + a3));
            l += e;
            unsigned long long ee = pack2(e, e);
            const ulonglong2* vp = (const ulonglong2*)&skv[mi][64 + h16];
            ulonglong2 v0 = vp[0]; FMA2(acc[0], ee, v0.x); FMA2(acc[1], ee, v0.y);
            ulonglong2 v1 = vp[1]; FMA2(acc[2], ee, v1.x); FMA2(acc[3], ee, v1.y);
            ulonglong2 v2 = vp[2]; FMA2(acc[4], ee, v2.x); FMA2(acc[5], ee, v2.y);
            ulonglong2 v3 = vp[3]; FMA2(acc[6], ee, v3.x); FMA2(acc[7], ee, v3.y);
        }
    }

    // ---- combine the two m-phases, normalize, write context ----
    float av[16];
#pragma unroll
    for (int j = 0; j < 8; j++) unpack2(acc[j], av[2 * j], av[2 * j + 1]);
    __syncthreads();
    if (p == 1) {
        sred[h][lane][0] = l;
#pragma unroll
        for (int j = 0; j < 16; j++) sred[h][lane][1 + j] = av[j];
    }
    __syncthreads();
    if (p == 0) {
        l += sred[h][lane][0];
        float inv = 1.0f / l;
#pragma unroll
        for (int j = 0; j < 16; j++) av[j] = (av[j] + sred[h][lane][1 + j]) * inv;
        float* dst = g_ctx + ((size_t)(b * NN + n)) * 64 + h16;
        *(float4*)(dst + 0)  = make_float4(av[0], av[1], av[2], av[3]);
        *(float4*)(dst + 4)  = make_float4(av[4], av[5], av[6], av[7]);
        *(float4*)(dst + 8)  = make_float4(av[8], av[9], av[10], av[11]);
        *(float4*)(dst + 12) = make_float4(av[12], av[13], av[14], av[15]);
    }
}

// -------------------- kernel 4: output projection + residual + LayerNorm --------------------
__global__ __launch_bounds__(256) void epi_kernel(const float* __restrict__ feats,
                                                  const float* __restrict__ ln_g,
                                                  const float* __restrict__ ln_b,
                                                  float* __restrict__ out, int out_size) {
    __shared__ float4 sWo[64][16];
    __shared__ float sctx[16][64];
    int tid = threadIdx.x;
    int row0 = blockIdx.x * 16;
    for (int idx = tid; idx < 64 * 16; idx += 256)
        sWo[idx >> 4][idx & 15] = ((const float4*)g_Wo)[idx];
    for (int idx = tid; idx < 16 * 64; idx += 256)
        sctx[idx >> 6][idx & 63] = g_ctx[(size_t)row0 * 64 + idx];
    __syncthreads();
    int r = tid >> 4, cg = tid & 15;  // 16 rows x 16 col-groups (4 cols each)
    int row = row0 + r;
    float4 y = ((const float4*)g_bo)[cg];
#pragma unroll 8
    for (int c = 0; c < 64; c++) {
        float f = sctx[r][c];
        float4 wv = sWo[c][cg];
        y.x += f * wv.x; y.y += f * wv.y; y.z += f * wv.z; y.w += f * wv.w;
    }
    float4 res = *(const float4*)(feats + (size_t)row * 64 + cg * 4);
    y.x += res.x; y.y += res.y; y.z += res.z; y.w += res.w;
    float s1 = y.x + y.y + y.z + y.w;
    float s2 = y.x * y.x + y.y * y.y + y.z * y.z + y.w * y.w;
#pragma unroll
    for (int off = 8; off; off >>= 1) {
        s1 += __shfl_xor_sync(0xffffffffu, s1, off);
        s2 += __shfl_xor_sync(0xffffffffu, s2, off);
    }
    float mu = s1 * (1.f / 64.f);
    float var = s2 * (1.f / 64.f) - mu * mu;
    float rs = rsqrtf(var + 1e-5f);
    float4 g4 = *(const float4*)(ln_g + cg * 4);
    float4 b4 = *(const float4*)(ln_b + cg * 4);
    float4 o;
    o.x = (y.x - mu) * rs * g4.x + b4.x;
    o.y = (y.y - mu) * rs * g4.y + b4.y;
    o.z = (y.z - mu) * rs * g4.z + b4.z;
    o.w = (y.w - mu) * rs * g4.w + b4.w;
    *(float4*)(out + (size_t)row * 64 + cg * 4) = o;
    // reg_loss = 1e-5 * mean(|softmax|) == 1e-5 / N exactly (rows sum to 1, all >= 0)
    if (blockIdx.x == 0 && tid == 0) {
        for (int idx = BB * NN * FF; idx < out_size; idx++)
            out[idx] = 1e-5f / 2048.f;
    }
}

// -------------------- launch --------------------
extern "C" void kernel_launch(void* const* d_in, const int* in_sizes, int n_in,
                              void* d_out, int out_size) {
    const float* feats   = (const float*)d_in[0];
    const float* fixedg  = (const float*)d_in[1];
    const float* learned = (const float*)d_in[2];
    const float* Wqc = (const float*)d_in[3];
    const float* bqc = (const float*)d_in[4];
    const float* Wqe = (const float*)d_in[5];
    const float* bqe = (const float*)d_in[6];
    const float* Woc = (const float*)d_in[7];
    const float* boc = (const float*)d_in[8];
    const float* Woe = (const float*)d_in[9];
    const float* boe = (const float*)d_in[10];
    const float* bf1 = (const float*)d_in[11];
    const float* bf2 = (const float*)d_in[12];
    const float* gf  = (const float*)d_in[13];
    const float* lng = (const float*)d_in[14];
    const float* lnb = (const float*)d_in[15];
    float* out = (float*)d_out;

    prep_kernel<<<1, 256>>>(Wqc, bqc, Wqe, bqe, Woc, boc, Woe, boe, gf);
    qkv_kernel<<<BB * NN / 32, 256>>>(feats);
    attn_kernel<<<BB * NN / 32, 256>>>(learned, fixedg, bf1, bf2);
    epi_kernel<<<BB * NN / 16, 256>>>(feats, lng, lnb, out, out_size);
}

// round 2
// speedup vs baseline: 1.3204x; 1.3204x over previous
#include <cuda_runtime.h>

#define BB 4
#define NN 2048
#define FF 64
#define HH 4
#define LOG2E 1.4426950408889634f

// -------------------- device scratch (no allocations allowed) --------------------
__device__ float g_Wqkv[64 * 192];      // fused Wqc@Wqe, q-cols pre-scaled by 0.25*log2e
__device__ float g_bqkv[192];           // fused bqc@Wqe + bqe (q part scaled)
__device__ float g_Wo[64 * 64];         // fused Woc@Woe
__device__ float g_bo[64];              // fused boc@Woe + boe
__device__ float g_fr[2];               // {sigmoid*log2e, (1-sigmoid)*log2e}
__device__ float g_qkv[BB * NN * 192];  // [b][n][q(64) k(64) v(64)]
__device__ float g_ctx[BB * NN * 64];   // attention context

// -------------------- f32x2 helpers (Blackwell packed fp32) --------------------
__device__ __forceinline__ unsigned long long pack2(float x, float y) {
    unsigned long long r;
    asm("mov.b64 %0, {%1, %2};" : "=l"(r) : "f"(x), "f"(y));
    return r;
}
__device__ __forceinline__ void unpack2(unsigned long long v, float& x, float& y) {
    asm("mov.b64 {%0, %1}, %2;" : "=f"(x), "=f"(y) : "l"(v));
}
#define FMA2(d, a, b) asm("fma.rn.f32x2 %0, %1, %2, %0;" : "+l"(d) : "l"(a), "l"(b))
__device__ __forceinline__ float ex2f(float x) {
    float y;
    asm("ex2.approx.f32 %0, %1;" : "=f"(y) : "f"(x));
    return y;
}

// -------------------- kernel 1: fold the low-rank projections --------------------
__global__ void prep_kernel(const float* __restrict__ Wqc, const float* __restrict__ bqc,
                            const float* __restrict__ Wqe, const float* __restrict__ bqe,
                            const float* __restrict__ Woc, const float* __restrict__ boc,
                            const float* __restrict__ Woe, const float* __restrict__ boe,
                            const float* __restrict__ gf) {
    int gtid = blockIdx.x * 256 + threadIdx.x;
    int gstr = gridDim.x * 256;
    const float QSCALE = 0.25f * LOG2E;  // fold 1/sqrt(hd) and log2e into q
    for (int idx = gtid; idx < 64 * 192; idx += gstr) {
        int i = idx / 192, j = idx % 192;
        float s = 0.f;
#pragma unroll
        for (int c = 0; c < 24; c++) s += Wqc[i * 24 + c] * Wqe[c * 192 + j];
        if (j < 64) s *= QSCALE;
        g_Wqkv[idx] = s;
    }
    for (int j = gtid; j < 192; j += gstr) {
        float s = bqe[j];
#pragma unroll
        for (int c = 0; c < 24; c++) s += bqc[c] * Wqe[c * 192 + j];
        if (j < 64) s *= QSCALE;
        g_bqkv[j] = s;
    }
    for (int idx = gtid; idx < 64 * 64; idx += gstr) {
        int i = idx >> 6, j = idx & 63;
        float s = 0.f;
#pragma unroll
        for (int c = 0; c < 8; c++) s += Woc[i * 8 + c] * Woe[c * 64 + j];
        g_Wo[idx] = s;
    }
    for (int j = gtid; j < 64; j += gstr) {
        float s = boe[j];
#pragma unroll
        for (int c = 0; c < 8; c++) s += boc[c] * Woe[c * 64 + j];
        g_bo[j] = s;
    }
    if (gtid == 0) {
        float fr = 1.f / (1.f + expf(-gf[0]));
        g_fr[0] = fr * LOG2E;
        g_fr[1] = (1.f - fr) * LOG2E;
    }
}

// -------------------- kernel 2: fused QKV projection --------------------
__global__ __launch_bounds__(256) void qkv_kernel(const float* __restrict__ feats) {
    __shared__ float sf[32][64];
    __shared__ float4 sW4[64][48];  // 192 floats per row
    int tid = threadIdx.x;
    int row0 = blockIdx.x * 32;
    for (int idx = tid; idx < 64 * 48; idx += 256)
        sW4[idx / 48][idx % 48] = ((const float4*)g_Wqkv)[idx];
    for (int idx = tid; idx < 32 * 64; idx += 256)
        sf[idx >> 6][idx & 63] = feats[(size_t)row0 * 64 + idx];
    __syncthreads();
    int r = tid >> 3, cg = tid & 7;  // 32 rows x 8 col-groups (24 cols each)
    float4 acc[6];
#pragma unroll
    for (int w = 0; w < 6; w++) acc[w] = ((const float4*)g_bqkv)[cg * 6 + w];
#pragma unroll 8
    for (int c = 0; c < 64; c++) {
        float f = sf[r][c];
#pragma unroll
        for (int w = 0; w < 6; w++) {
            float4 wv = sW4[c][cg * 6 + w];
            acc[w].x += f * wv.x; acc[w].y += f * wv.y;
            acc[w].z += f * wv.z; acc[w].w += f * wv.w;
        }
    }
    float4* dst = (float4*)&g_qkv[(size_t)(row0 + r) * 192 + cg * 24];
#pragma unroll
    for (int w = 0; w < 6; w++) dst[w] = acc[w];
}

// -------------------- kernel 3: fused attention (the hot kernel) --------------------
// Grid: 256 CTAs (b x 32-row blocks). CTA: 256 threads = 8 warps.
// Warp w: head h = w&3, phase p = w>>2 (contiguous 16-m half per phase).
// Lane = row within the 32-row block. All k/v/bf2 shared reads are warp-uniform
// (pure broadcast). Scores are small -> no max subtraction needed.
// Software pipelined: prefetch tile t+1 into registers while computing tile t,
// double-buffered smem.
__global__ __launch_bounds__(256, 2) void attn_kernel(const float* __restrict__ learned,
                                                      const float* __restrict__ fixedg,
                                                      const float* __restrict__ bf1,
                                                      const float* __restrict__ bf2) {
    __shared__ float skv[2][32][128];    // k (0..63) | v (64..127) per m
    __shared__ float scomb[2][32][33];   // fused graph (pre-scaled by log2e)
    __shared__ float sbf2[2][4][32][8];  // bias factor 2, [h][mi][c]
    __shared__ float sred[4][32][17];    // phase-combine buffer {l, acc[16]}

    int tid = threadIdx.x;
    int lane = tid & 31;
    int w = tid >> 5;
    int h = w & 3, p = w >> 2;
    int bid = blockIdx.x;
    int b = bid >> 6;             // 64 row-blocks per batch
    int n0 = (bid & 63) << 5;     // 32 rows per CTA
    int n = n0 + lane;
    int h16 = h * 16;
    int mbase = p << 4;           // contiguous 16-m half

    // preload q (pre-scaled by 0.25*log2e) and bf1 row (scale log2e here)
    unsigned long long q2[8], f1p[4];
    {
        const ulonglong2* qp = (const ulonglong2*)(g_qkv + ((size_t)(b * NN + n)) * 192 + h16);
        ulonglong2 a0 = qp[0], a1 = qp[1], a2 = qp[2], a3 = qp[3];
        q2[0] = a0.x; q2[1] = a0.y; q2[2] = a1.x; q2[3] = a1.y;
        q2[4] = a2.x; q2[5] = a2.y; q2[6] = a3.x; q2[7] = a3.y;
        const float4* fp4 = (const float4*)(bf1 + ((size_t)h * NN + n) * 8);
        float4 fa = fp4[0], fb = fp4[1];
        f1p[0] = pack2(fa.x * LOG2E, fa.y * LOG2E);
        f1p[1] = pack2(fa.z * LOG2E, fa.w * LOG2E);
        f1p[2] = pack2(fb.x * LOG2E, fb.y * LOG2E);
        f1p[3] = pack2(fb.z * LOG2E, fb.w * LOG2E);
    }
    float fr2 = g_fr[0];
    float fr12 = g_fr[1];

    // per-thread cooperative-load decompositions (fixed across tiles)
    int kv_mi = tid >> 5, kv_j4 = tid & 31;          // kv fill
    int gr_r = tid >> 3, gr_c = tid & 7;             // graph fill
    int bf_h = tid >> 6, bf_c = (tid & 63) >> 3, bf_m = tid & 7;  // bf2 fill

    const float* kvp = g_qkv + ((size_t)(b * NN + kv_mi)) * 192 + 64 + kv_j4 * 4;
    const float* lp = learned + ((size_t)(b * NN + n0 + gr_r)) * NN + gr_c * 4;
    const float* fp = fixedg + ((size_t)(n0 + gr_r)) * NN + gr_c * 4;
    const float* bp = bf2 + ((size_t)(bf_h * 8 + bf_c)) * NN + bf_m * 4;

    unsigned long long acc[8];
#pragma unroll
    for (int j = 0; j < 8; j++) acc[j] = 0ULL;
    float l = 0.f;

    float4 rkv0, rkv1, rkv2, rkv3, rl4, rf4, rb4;
#define PREFETCH(M0)                                            \
    do {                                                        \
        const float* kq = kvp + (size_t)(M0) * 192;             \
        rkv0 = *(const float4*)(kq);                            \
        rkv1 = *(const float4*)(kq + 8 * 192);                  \
        rkv2 = *(const float4*)(kq + 16 * 192);                 \
        rkv3 = *(const float4*)(kq + 24 * 192);                 \
        rl4 = *(const float4*)(lp + (M0));                      \
        rf4 = *(const float4*)(fp + (M0));                      \
        rb4 = *(const float4*)(bp + (M0));                      \
    } while (0)

#define STORE_TILE(NB)                                          \
    do {                                                        \
        *(float4*)&skv[NB][kv_mi][kv_j4 * 4] = rkv0;            \
        *(float4*)&skv[NB][kv_mi + 8][kv_j4 * 4] = rkv1;        \
        *(float4*)&skv[NB][kv_mi + 16][kv_j4 * 4] = rkv2;       \
        *(float4*)&skv[NB][kv_mi + 24][kv_j4 * 4] = rkv3;       \
        scomb[NB][gr_r][gr_c * 4 + 0] = fr2 * rl4.x + fr12 * rf4.x; \
        scomb[NB][gr_r][gr_c * 4 + 1] = fr2 * rl4.y + fr12 * rf4.y; \
        scomb[NB][gr_r][gr_c * 4 + 2] = fr2 * rl4.z + fr12 * rf4.z; \
        scomb[NB][gr_r][gr_c * 4 + 3] = fr2 * rl4.w + fr12 * rf4.w; \
        sbf2[NB][bf_h][bf_m * 4 + 0][bf_c] = rb4.x;             \
        sbf2[NB][bf_h][bf_m * 4 + 1][bf_c] = rb4.y;             \
        sbf2[NB][bf_h][bf_m * 4 + 2][bf_c] = rb4.z;             \
        sbf2[NB][bf_h][bf_m * 4 + 3][bf_c] = rb4.w;             \
    } while (0)

    // preamble: fill buffer 0 with tile 0
    PREFETCH(0);
    STORE_TILE(0);
    __syncthreads();

    for (int t = 0; t < 64; t++) {
        int cb = t & 1;
        if (t < 63) PREFETCH((t + 1) * 32);   // overlaps with compute below

        // ---- inner loop: 16 m per warp (contiguous phase half) ----
#pragma unroll 4
        for (int i = 0; i < 16; i++) {
            int mi = mbase + i;
            unsigned long long s0 = pack2(scomb[cb][lane][mi], 0.f), s1 = 0ULL;
            const ulonglong2* kp = (const ulonglong2*)&skv[cb][mi][h16];
            ulonglong2 t0 = kp[0]; FMA2(s0, q2[0], t0.x); FMA2(s1, q2[1], t0.y);
            ulonglong2 t1 = kp[1]; FMA2(s0, q2[2], t1.x); FMA2(s1, q2[3], t1.y);
            ulonglong2 t2 = kp[2]; FMA2(s0, q2[4], t2.x); FMA2(s1, q2[5], t2.y);
            ulonglong2 t3 = kp[3]; FMA2(s0, q2[6], t3.x); FMA2(s1, q2[7], t3.y);
            const ulonglong2* bpp = (const ulonglong2*)&sbf2[cb][h][mi][0];
            ulonglong2 u0 = bpp[0]; FMA2(s0, f1p[0], u0.x); FMA2(s1, f1p[1], u0.y);
            ulonglong2 u1 = bpp[1]; FMA2(s0, f1p[2], u1.x); FMA2(s1, f1p[3], u1.y);
            float a0, a1, a2, a3;
            unpack2(s0, a0, a1); unpack2(s1, a2, a3);
            float e = ex2f((a0 + a2) + (a1 + a3));
            l += e;
            unsigned long long ee = pack2(e, e);
            const ulonglong2* vp = (const ulonglong2*)&skv[cb][mi][64 + h16];
            ulonglong2 v0 = vp[0]; FMA2(acc[0], ee, v0.x); FMA2(acc[1], ee, v0.y);
            ulonglong2 v1 = vp[1]; FMA2(acc[2], ee, v1.x); FMA2(acc[3], ee, v1.y);
            ulonglong2 v2 = vp[2]; FMA2(acc[4], ee, v2.x); FMA2(acc[5], ee, v2.y);
            ulonglong2 v3 = vp[3]; FMA2(acc[6], ee, v3.x); FMA2(acc[7], ee, v3.y);
        }
        __syncthreads();               // all warps done reading buf cb (and cb^1 from t-1)
        if (t < 63) {
            STORE_TILE(cb ^ 1);
            __syncthreads();           // publish buf cb^1 for tile t+1
        }
    }
#undef PREFETCH
#undef STORE_TILE

    // ---- combine the two m-phases, normalize, write context ----
    float av[16];
#pragma unroll
    for (int j = 0; j < 8; j++) unpack2(acc[j], av[2 * j], av[2 * j + 1]);
    __syncthreads();
    if (p == 1) {
        sred[h][lane][0] = l;
#pragma unroll
        for (int j = 0; j < 16; j++) sred[h][lane][1 + j] = av[j];
    }
    __syncthreads();
    if (p == 0) {
        l += sred[h][lane][0];
        float inv = 1.0f / l;
#pragma unroll
        for (int j = 0; j < 16; j++) av[j] = (av[j] + sred[h][lane][1 + j]) * inv;
        float* dst = g_ctx + ((size_t)(b * NN + n)) * 64 + h16;
        *(float4*)(dst + 0)  = make_float4(av[0], av[1], av[2], av[3]);
        *(float4*)(dst + 4)  = make_float4(av[4], av[5], av[6], av[7]);
        *(float4*)(dst + 8)  = make_float4(av[8], av[9], av[10], av[11]);
        *(float4*)(dst + 12) = make_float4(av[12], av[13], av[14], av[15]);
    }
}

// -------------------- kernel 4: output projection + residual + LayerNorm --------------------
__global__ __launch_bounds__(256) void epi_kernel(const float* __restrict__ feats,
                                                  const float* __restrict__ ln_g,
                                                  const float* __restrict__ ln_b,
                                                  float* __restrict__ out, int out_size) {
    __shared__ float4 sWo[64][16];
    __shared__ float sctx[16][64];
    int tid = threadIdx.x;
    int row0 = blockIdx.x * 16;
    for (int idx = tid; idx < 64 * 16; idx += 256)
        sWo[idx >> 4][idx & 15] = ((const float4*)g_Wo)[idx];
    for (int idx = tid; idx < 16 * 64; idx += 256)
        sctx[idx >> 6][idx & 63] = g_ctx[(size_t)row0 * 64 + idx];
    __syncthreads();
    int r = tid >> 4, cg = tid & 15;  // 16 rows x 16 col-groups (4 cols each)
    int row = row0 + r;
    float4 y = ((const float4*)g_bo)[cg];
#pragma unroll 8
    for (int c = 0; c < 64; c++) {
        float f = sctx[r][c];
        float4 wv = sWo[c][cg];
        y.x += f * wv.x; y.y += f * wv.y; y.z += f * wv.z; y.w += f * wv.w;
    }
    float4 res = *(const float4*)(feats + (size_t)row * 64 + cg * 4);
    y.x += res.x; y.y += res.y; y.z += res.z; y.w += res.w;
    float s1 = y.x + y.y + y.z + y.w;
    float s2 = y.x * y.x + y.y * y.y + y.z * y.z + y.w * y.w;
#pragma unroll
    for (int off = 8; off; off >>= 1) {
        s1 += __shfl_xor_sync(0xffffffffu, s1, off);
        s2 += __shfl_xor_sync(0xffffffffu, s2, off);
    }
    float mu = s1 * (1.f / 64.f);
    float var = s2 * (1.f / 64.f) - mu * mu;
    float rs = rsqrtf(var + 1e-5f);
    float4 g4 = *(const float4*)(ln_g + cg * 4);
    float4 b4 = *(const float4*)(ln_b + cg * 4);
    float4 o;
    o.x = (y.x - mu) * rs * g4.x + b4.x;
    o.y = (y.y - mu) * rs * g4.y + b4.y;
    o.z = (y.z - mu) * rs * g4.z + b4.z;
    o.w = (y.w - mu) * rs * g4.w + b4.w;
    *(float4*)(out + (size_t)row * 64 + cg * 4) = o;
    // reg_loss = 1e-5 * mean(|softmax|) == 1e-5 / N exactly (rows sum to 1, all >= 0)
    if (blockIdx.x == 0 && tid == 0) {
        for (int idx = BB * NN * FF; idx < out_size; idx++)
            out[idx] = 1e-5f / 2048.f;
    }
}

// -------------------- launch --------------------
extern "C" void kernel_launch(void* const* d_in, const int* in_sizes, int n_in,
                              void* d_out, int out_size) {
    const float* feats   = (const float*)d_in[0];
    const float* fixedg  = (const float*)d_in[1];
    const float* learned = (const float*)d_in[2];
    const float* Wqc = (const float*)d_in[3];
    const float* bqc = (const float*)d_in[4];
    const float* Wqe = (const float*)d_in[5];
    const float* bqe = (const float*)d_in[6];
    const float* Woc = (const float*)d_in[7];
    const float* boc = (const float*)d_in[8];
    const float* Woe = (const float*)d_in[9];
    const float* boe = (const float*)d_in[10];
    const float* bf1 = (const float*)d_in[11];
    const float* bf2 = (const float*)d_in[12];
    const float* gf  = (const float*)d_in[13];
    const float* lng = (const float*)d_in[14];
    const float* lnb = (const float*)d_in[15];
    float* out = (float*)d_out;

    prep_kernel<<<48, 256>>>(Wqc, bqc, Wqe, bqe, Woc, boc, Woe, boe, gf);
    qkv_kernel<<<BB * NN / 32, 256>>>(feats);
    attn_kernel<<<BB * NN / 32, 256>>>(learned, fixedg, bf1, bf2);
    epi_kernel<<<BB * NN / 16, 256>>>(feats, lng, lnb, out, out_size);
}